// round 5
// baseline (speedup 1.0000x reference)
#include <cuda_runtime.h>
#include <cuda_bf16.h>
#include <cuda_fp16.h>
#include <math.h>
#include <stdint.h>

#define NN 50000
#define NE 800000
#define FIN 64
#define DD 128
#define NL 3
#define NB 8
#define POOL_C 64
#define NBLK 196          // ceil(NN/256)
#define WTOT 122880       // 128*64 + 3*128*256 + 128*128
#define NXP  1600000      // NN*FIN/2
#define ASTRIDE 72
#define ST_BYTES 73728    // 4 * 128*72*2
#define OFF_AH 0
#define OFF_AL 18432
#define OFF_BH 36864
#define OFF_BL 55296
#define SMEM_DYN (2 * ST_BYTES)

// ---------------- scratch (device globals; no allocation) ----------------
__device__ __align__(16) __nv_bfloat16 g_hbh[NN * DD];   // h bf16 hi
__device__ __align__(16) __nv_bfloat16 g_hbl[NN * DD];   // h bf16 lo
__device__ __align__(16) __half g_hh[NN * DD];           // h fp16 (gathers)
__device__ __align__(16) __nv_bfloat16 g_abh[NN * DD];   // agg hi
__device__ __align__(16) __nv_bfloat16 g_abl[NN * DD];   // agg lo
__device__ __align__(16) __nv_bfloat16 g_xbh[NN * FIN];
__device__ __align__(16) __nv_bfloat16 g_xbl[NN * FIN];
__device__ __align__(16) __nv_bfloat16 g_wbh[WTOT];      // weights [n][k] hi
__device__ __align__(16) __nv_bfloat16 g_wbl[WTOT];      // lo
__device__ int   g_cnt[NN];
__device__ int   g_inc[NBLK * 256];
__device__ int   g_blksum[NBLK];
__device__ int   g_rowptr[NN + 1];
__device__ int   g_cursor[NN];
__device__ int   g_col[NE];
__device__ float g_deg[NN];
__device__ float g_logit[NN];
__device__ float g_sumexp;
__device__ int   g_bstart[NB + 1];
__device__ float g_pooled[NB * DD];

// ---------------- helpers ----------------
__device__ __forceinline__ float geluf(float x) {
    return 0.5f * x * (1.0f + erff(x * 0.7071067811865476f));
}
__device__ __forceinline__ float wsum(float v) {
#pragma unroll
    for (int o = 16; o > 0; o >>= 1) v += __shfl_xor_sync(0xffffffffu, v, o);
    return v;
}
__device__ __forceinline__ int wsumi(int v) {
#pragma unroll
    for (int o = 16; o > 0; o >>= 1) v += __shfl_xor_sync(0xffffffffu, v, o);
    return v;
}
__device__ __forceinline__ float qsum(float v) {
    v += __shfl_xor_sync(0xffffffffu, v, 1);
    v += __shfl_xor_sync(0xffffffffu, v, 2);
    return v;
}
__device__ __forceinline__ float4 ln128w(float4 v, const float* __restrict__ g,
                                         const float* __restrict__ b, int lane) {
    float m = wsum(v.x + v.y + v.z + v.w) * (1.0f / 128.0f);
    float dx = v.x - m, dy = v.y - m, dz = v.z - m, dw = v.w - m;
    float var = wsum(dx * dx + dy * dy + dz * dz + dw * dw) * (1.0f / 128.0f);
    float rs = rsqrtf(var + 1e-5f);
    float4 gg = *reinterpret_cast<const float4*>(g + lane * 4);
    float4 bb = *reinterpret_cast<const float4*>(b + lane * 4);
    return make_float4(dx * rs * gg.x + bb.x, dy * rs * gg.y + bb.y,
                       dz * rs * gg.z + bb.z, dw * rs * gg.w + bb.w);
}
__device__ __forceinline__ uint32_t smem_u32(const void* p) {
    uint32_t a;
    asm("{ .reg .u64 t; cvta.to.shared.u64 t, %1; cvt.u32.u64 %0, t; }" : "=r"(a) : "l"(p));
    return a;
}
__device__ __forceinline__ void ldm4(uint32_t* r, uint32_t addr) {
    asm volatile("ldmatrix.sync.aligned.m8n8.x4.shared.b16 {%0,%1,%2,%3}, [%4];"
                 : "=r"(r[0]), "=r"(r[1]), "=r"(r[2]), "=r"(r[3]) : "r"(addr));
}
__device__ __forceinline__ void mma16816(float* d, const uint32_t* a, uint32_t b0, uint32_t b1) {
    asm volatile(
        "mma.sync.aligned.m16n8k16.row.col.f32.bf16.bf16.f32 "
        "{%0,%1,%2,%3}, {%4,%5,%6,%7}, {%8,%9}, {%0,%1,%2,%3};"
        : "+f"(d[0]), "+f"(d[1]), "+f"(d[2]), "+f"(d[3])
        : "r"(a[0]), "r"(a[1]), "r"(a[2]), "r"(a[3]), "r"(b0), "r"(b1));
}
// pack two floats to bf16x2 (v0 -> low half, v1 -> high half)
__device__ __forceinline__ uint32_t cvt2(float v0, float v1) {
    uint32_t d;
    asm("cvt.rn.bf16x2.f32 %0, %1, %2;" : "=r"(d) : "f"(v1), "f"(v0));
    return d;
}
// hi/lo split of a float pair, packed
__device__ __forceinline__ void split_pair(float v0, float v1, uint32_t& hi, uint32_t& lo) {
    hi = cvt2(v0, v1);
    float f0 = __uint_as_float(hi << 16);
    float f1 = __uint_as_float(hi & 0xFFFF0000u);
    lo = cvt2(v0 - f0, v1 - f1);
}
#define CP16(dst, src, sz) \
    asm volatile("cp.async.cg.shared.global [%0], [%1], 16, %2;" \
                 :: "r"(dst), "l"(src), "r"(sz) : "memory")
#define CP_COMMIT() asm volatile("cp.async.commit_group;" ::: "memory")
#define CP_WAIT0()  asm volatile("cp.async.wait_group 0;" ::: "memory")
#define CP_WAIT1()  asm volatile("cp.async.wait_group 1;" ::: "memory")

// ---------------- init: zero counters + split weights and x ----------------
__global__ void k_init(const float* __restrict__ x, const float* __restrict__ w_in,
                       const float* __restrict__ gnn_w, const float* __restrict__ gate_w1) {
    int i = blockIdx.x * blockDim.x + threadIdx.x;
    if (i < NXP) {
        float2 v = reinterpret_cast<const float2*>(x)[i];
        uint32_t hi, lo;
        split_pair(v.x, v.y, hi, lo);
        reinterpret_cast<uint32_t*>(g_xbh)[i] = hi;
        reinterpret_cast<uint32_t*>(g_xbl)[i] = lo;
    }
    if (i < WTOT / 2) {
        int j = 2 * i;
        float v0, v1;
        if (j < 8192) {
            int n = j >> 6, k = j & 63;
            v0 = w_in[k * 128 + n];
            v1 = w_in[(k + 1) * 128 + n];
        } else if (j < 106496) {
            int jj = j - 8192;
            int l = jj >> 15, r = jj & 32767;
            int n = r >> 8, k = r & 255;
            v0 = gnn_w[((l << 8) + k) * 128 + n];
            v1 = gnn_w[((l << 8) + k + 1) * 128 + n];
        } else {
            int jj = j - 106496;
            int n = jj >> 7, k = jj & 127;
            v0 = gate_w1[k * 128 + n];
            v1 = gate_w1[(k + 1) * 128 + n];
        }
        uint32_t hi, lo;
        split_pair(v0, v1, hi, lo);
        reinterpret_cast<uint32_t*>(g_wbh)[i] = hi;
        reinterpret_cast<uint32_t*>(g_wbl)[i] = lo;
    }
    if (i < NN) g_cnt[i] = 0;
    if (i < NB * DD) g_pooled[i] = 0.0f;
    if (i == 0) g_sumexp = 0.0f;
}

// ---------------- CSR build ----------------
__global__ void k_count(const int* __restrict__ ei) {
    int e = blockIdx.x * blockDim.x + threadIdx.x;
    if (e < NE) atomicAdd(&g_cnt[ei[NE + e]], 1);
}
__global__ void k_scan1() {
    __shared__ int sw_[8];
    int b = blockIdx.x, t = threadIdx.x, i = b * 256 + t;
    int v = (i < NN) ? g_cnt[i] : 0;
    int x = v;
#pragma unroll
    for (int o = 1; o < 32; o <<= 1) {
        int y = __shfl_up_sync(0xffffffffu, x, o);
        if ((t & 31) >= o) x += y;
    }
    if ((t & 31) == 31) sw_[t >> 5] = x;
    __syncthreads();
    if (t == 0) {
        int s = 0;
        for (int w = 0; w < 8; w++) { int tmp = sw_[w]; sw_[w] = s; s += tmp; }
    }
    __syncthreads();
    int incl = x + sw_[t >> 5];
    g_inc[b * 256 + t] = incl;
    if (t == 255) g_blksum[b] = incl;
}
__global__ void k_scan3(const int* __restrict__ batch) {
    __shared__ int soff;
    int blk = blockIdx.x, t = threadIdx.x;
    if (t < 32) {
        int s = 0;
        for (int b = t; b < blk; b += 32) s += g_blksum[b];
        s = wsumi(s);
        if (t == 0) soff = s;
    }
    __syncthreads();
    int i = blk * 256 + t;
    if (i < NN) {
        int incl = g_inc[i] + soff;
        int v = g_cnt[i];
        g_rowptr[i + 1] = incl;
        g_cursor[i] = incl - v;
        g_deg[i] = (v > 0) ? (float)v : 1.0f;
        if (i == 0) g_rowptr[0] = 0;
    }
    if (blk == 0 && t <= NB) {
        int lo = 0, hi = NN;
        while (lo < hi) {
            int mid = (lo + hi) >> 1;
            if (batch[mid] < t) lo = mid + 1; else hi = mid;
        }
        g_bstart[t] = lo;
    }
}
__global__ void k_scatter(const int* __restrict__ ei) {
    int e = blockIdx.x * blockDim.x + threadIdx.x;
    if (e < NE) {
        int d = ei[NE + e];
        int p = atomicAdd(&g_cursor[d], 1);
        g_col[p] = ei[e];
    }
}

// ---------------- HMMA GEMM (bf16 hi/lo 3-pass), cp.async double-buffered ----------------
// MODE 0: input proj (A = g_xbh/g_xbl): +bias -> LN -> GELU -> store h
// MODE 1: GNN layer (A = [g_hbh|g_abh] etc): +bias -> GELU -> LN -> LN [-> GELU+res] -> store h
// MODE 2: gate (A = g_hbh/g_hbl): tanh(v+bias).w2 -> logit + exp-sum atomic
template <int KD, int MODE>
__global__ void __launch_bounds__(256, 1)
gemm_mma(const float* __restrict__ bias, const float* __restrict__ p1,
         const float* __restrict__ p2, const float* __restrict__ p3,
         const float* __restrict__ p4, float* __restrict__ aux,
         int boff, int residual, int nrows) {
    extern __shared__ __align__(16) char dyn[];
    __shared__ float s0[128], s1[128], s2[128], s3[128], s4[128];
    __shared__ float sred[8];

    const int t = threadIdx.x;
    const int lane = t & 31, w = t >> 5;
    const int row0 = blockIdx.x * 128;
    const uint32_t sb = smem_u32(dyn);

    if (t < 128) {
        s0[t] = bias[t];
        s1[t] = p1[t];
        if (MODE != 2) s2[t] = p2[t];
        if (MODE == 1) { s3[t] = p3[t]; s4[t] = p4[t]; }
    }

    constexpr int NCH = KD / 64;

    float acc[16][4];
#pragma unroll
    for (int i = 0; i < 16; i++)
#pragma unroll
        for (int j = 0; j < 4; j++) acc[i][j] = 0.0f;

    const int rr = t >> 3;       // 0..31 within q-group
    const int seg = t & 7;

    auto issue = [&](int c, int s) {
        const uint32_t stb = sb + s * ST_BYTES;
#pragma unroll
        for (int q = 0; q < 4; q++) {
            const int r = q * 32 + rr;
            const int row = row0 + r;
            const bool valid = row < nrows;
            const int rc = valid ? row : 0;
            const uint32_t sz = valid ? 16u : 0u;
            const __nv_bfloat16 *pah, *pal;
            if (MODE == 0) {
                pah = g_xbh + (size_t)rc * 64 + seg * 8;
                pal = g_xbl + (size_t)rc * 64 + seg * 8;
            } else if (MODE == 2) {
                pah = g_hbh + (size_t)rc * 128 + c * 64 + seg * 8;
                pal = g_hbl + (size_t)rc * 128 + c * 64 + seg * 8;
            } else if (c < 2) {
                pah = g_hbh + (size_t)rc * 128 + c * 64 + seg * 8;
                pal = g_hbl + (size_t)rc * 128 + c * 64 + seg * 8;
            } else {
                pah = g_abh + (size_t)rc * 128 + (c - 2) * 64 + seg * 8;
                pal = g_abl + (size_t)rc * 128 + (c - 2) * 64 + seg * 8;
            }
            const uint32_t doff = (r * ASTRIDE + seg * 8) * 2;
            CP16(stb + OFF_AH + doff, pah, sz);
            CP16(stb + OFF_AL + doff, pal, sz);
            const size_t wb = (size_t)boff + (size_t)r * KD + c * 64 + seg * 8;
            CP16(stb + OFF_BH + doff, g_wbh + wb, 16u);
            CP16(stb + OFF_BL + doff, g_wbl + wb, 16u);
        }
    };

    const uint32_t a_off = ((w * 16 + (lane & 15)) * ASTRIDE + (lane >> 4) * 8) * 2;
    const int bgq = lane >> 3;
    const uint32_t b_off = ((((bgq & 2) ? 8 : 0) + (lane & 7)) * ASTRIDE + ((bgq & 1) ? 8 : 0)) * 2;

    issue(0, 0);
    CP_COMMIT();
    for (int c = 0; c < NCH; c++) {
        if (c + 1 < NCH) {
            issue(c + 1, (c + 1) & 1);
            CP_COMMIT();
            CP_WAIT1();
        } else {
            CP_WAIT0();
        }
        __syncthreads();
        const uint32_t st = (uint32_t)(c & 1) * ST_BYTES;
        const uint32_t Ah = sb + st + OFF_AH + a_off;
        const uint32_t Al = sb + st + OFF_AL + a_off;
        const uint32_t Bh = sb + st + OFF_BH + b_off;
        const uint32_t Bl = sb + st + OFF_BL + b_off;
#pragma unroll
        for (int kk = 0; kk < 64; kk += 16) {
            uint32_t aH[4], aL[4];
            ldm4(aH, Ah + kk * 2);
            ldm4(aL, Al + kk * 2);
#pragma unroll
            for (int np = 0; np < 8; np++) {
                uint32_t bH[4], bL[4];
                uint32_t nb = (np * 16) * ASTRIDE * 2 + kk * 2;
                ldm4(bH, Bh + nb);
                ldm4(bL, Bl + nb);
                mma16816(acc[np * 2],     aH, bH[0], bH[1]);
                mma16816(acc[np * 2 + 1], aH, bH[2], bH[3]);
                mma16816(acc[np * 2],     aL, bH[0], bH[1]);
                mma16816(acc[np * 2 + 1], aL, bH[2], bH[3]);
                mma16816(acc[np * 2],     aH, bL[0], bL[1]);
                mma16816(acc[np * 2 + 1], aH, bL[2], bL[3]);
            }
        }
        __syncthreads();
    }

    // ---------------- fused epilogue ----------------
    const int qd = lane & 3;
    float esum = 0.f;
#pragma unroll
    for (int ri = 0; ri < 2; ri++) {
        const int row = row0 + w * 16 + (lane >> 2) + ri * 8;
        const bool ok = row < nrows;

        if (MODE == 2) {
            float p = 0.f;
#pragma unroll
            for (int j = 0; j < 32; j++) {
                int n = (j >> 1) * 8 + qd * 2 + (j & 1);
                p += tanhf(acc[j >> 1][ri * 2 + (j & 1)] + s0[n]) * s1[n];
            }
            p = qsum(p);
            if (qd == 0 && ok) {
                float lg = p + p3[0];
                g_logit[row] = lg;
                esum += expf(lg);
            }
            continue;
        }

        float v[32];
        float sum = 0.f;
#pragma unroll
        for (int j = 0; j < 32; j++) {
            int n = (j >> 1) * 8 + qd * 2 + (j & 1);
            float u = acc[j >> 1][ri * 2 + (j & 1)] + s0[n];
            if (MODE == 1) u = geluf(u);
            v[j] = u;
            sum += u;
        }
        float m1 = qsum(sum) * (1.0f / 128.0f);
        float var = 0.f;
#pragma unroll
        for (int j = 0; j < 32; j++) { float d = v[j] - m1; var += d * d; }
        float rs = rsqrtf(qsum(var) * (1.0f / 128.0f) + 1e-5f);

        if (MODE == 0) {
            if (ok) {
                uint32_t* ph = (uint32_t*)(g_hbh + (size_t)row * 128);
                uint32_t* pl = (uint32_t*)(g_hbl + (size_t)row * 128);
                uint32_t* phh = (uint32_t*)(g_hh + (size_t)row * 128);
#pragma unroll
                for (int k = 0; k < 16; k++) {
                    int n = k * 8 + qd * 2;
                    float o0 = geluf((v[2 * k] - m1) * rs * s1[n] + s2[n]);
                    float o1 = geluf((v[2 * k + 1] - m1) * rs * s1[n + 1] + s2[n + 1]);
                    uint32_t hi, lo;
                    split_pair(o0, o1, hi, lo);
                    ph[n >> 1] = hi;
                    pl[n >> 1] = lo;
                    __half2 hp = __floats2half2_rn(o0, o1);
                    phh[n >> 1] = *reinterpret_cast<uint32_t*>(&hp);
                }
            }
            continue;
        }

        // MODE 1: second LN
        float sum2 = 0.f;
#pragma unroll
        for (int j = 0; j < 32; j++) {
            int n = (j >> 1) * 8 + qd * 2 + (j & 1);
            float u = (v[j] - m1) * rs * s1[n] + s2[n];
            v[j] = u;
            sum2 += u;
        }
        float m2 = qsum(sum2) * (1.0f / 128.0f);
        float var2 = 0.f;
#pragma unroll
        for (int j = 0; j < 32; j++) { float d = v[j] - m2; var2 += d * d; }
        float rs2 = rsqrtf(qsum(var2) * (1.0f / 128.0f) + 1e-5f);

        if (ok) {
            uint32_t* ph = (uint32_t*)(g_hbh + (size_t)row * 128);
            uint32_t* pl = (uint32_t*)(g_hbl + (size_t)row * 128);
            uint32_t* phh = (uint32_t*)(g_hh + (size_t)row * 128);
            float2* arow = aux ? (float2*)(aux + (size_t)row * 128) : nullptr;
#pragma unroll
            for (int k = 0; k < 16; k++) {
                int n = k * 8 + qd * 2;
                float o0 = (v[2 * k] - m2) * rs2 * s3[n] + s4[n];
                float o1 = (v[2 * k + 1] - m2) * rs2 * s3[n + 1] + s4[n + 1];
                if (residual) {
                    uint32_t hprev = ph[n >> 1];
                    uint32_t lprev = pl[n >> 1];
                    float h0 = __uint_as_float(hprev << 16) + __uint_as_float(lprev << 16);
                    float h1 = __uint_as_float(hprev & 0xFFFF0000u) +
                               __uint_as_float(lprev & 0xFFFF0000u);
                    o0 = geluf(o0) + h0;
                    o1 = geluf(o1) + h1;
                }
                uint32_t hi, lo;
                split_pair(o0, o1, hi, lo);
                ph[n >> 1] = hi;
                pl[n >> 1] = lo;
                __half2 hp = __floats2half2_rn(o0, o1);
                phh[n >> 1] = *reinterpret_cast<uint32_t*>(&hp);
                if (arow) arow[n >> 1] = make_float2(o0, o1);
            }
        }
    }

    if (MODE == 2) {
        esum = wsum(esum);
        if (lane == 0) sred[w] = esum;
        __syncthreads();
        if (t == 0) {
            float tot = 0.f;
            for (int i = 0; i < 8; i++) tot += sred[i];
            atomicAdd(&g_sumexp, tot);
        }
    }
}

// ---------------- aggregation: mean over CSR neighbors (fp16 gather) -> bf16 hi/lo ----------------
__global__ void k_aggregate() {
    int gid = blockIdx.x * blockDim.x + threadIdx.x;
    int node = gid >> 5, lane = gid & 31;
    if (node >= NN) return;
    int s = g_rowptr[node], e = g_rowptr[node + 1];
    float4 acc = make_float4(0.f, 0.f, 0.f, 0.f);
    const uint2* hh = reinterpret_cast<const uint2*>(g_hh);
    for (int i = s; i < e; i++) {
        int src = g_col[i];
        uint2 v = hh[(size_t)src * 32 + lane];
        float2 f0 = __half22float2(*reinterpret_cast<__half2*>(&v.x));
        float2 f1 = __half22float2(*reinterpret_cast<__half2*>(&v.y));
        acc.x += f0.x; acc.y += f0.y; acc.z += f1.x; acc.w += f1.y;
    }
    float inv = 1.0f / g_deg[node];
    acc.x *= inv; acc.y *= inv; acc.z *= inv; acc.w *= inv;
    uint32_t h0, l0, h1, l1;
    split_pair(acc.x, acc.y, h0, l0);
    split_pair(acc.z, acc.w, h1, l1);
    size_t base = (size_t)node * 32 + lane;
    reinterpret_cast<uint2*>(g_abh)[base] = make_uint2(h0, h1);
    reinterpret_cast<uint2*>(g_abl)[base] = make_uint2(l0, l1);
}

// ---------------- pooling (gate inline, atomic accumulate) ----------------
__global__ void k_pool(float* __restrict__ out_gate) {
    int b = blockIdx.x / POOL_C;
    int c = blockIdx.x % POOL_C;
    int s = g_bstart[b], e = g_bstart[b + 1];
    long long len = e - s;
    int cs = s + (int)(len * c / POOL_C);
    int ce = s + (int)(len * (c + 1) / POOL_C);
    int d = threadIdx.x;
    float inv = 1.0f / g_sumexp;
    float acc = 0.f;
    for (int n = cs; n < ce; n++) {
        float gv = expf(g_logit[n]) * inv;
        float h = __bfloat162float(g_hbh[(size_t)n * DD + d]) +
                  __bfloat162float(g_hbl[(size_t)n * DD + d]);
        acc += gv * h;
        if (d == 0 && out_gate) out_gate[n] = gv;
    }
    atomicAdd(&g_pooled[b * DD + d], acc);
}

// ---------------- final out proj ----------------
__global__ void k_out(const float* __restrict__ W, const float* __restrict__ bias,
                      const float* __restrict__ lg, const float* __restrict__ lb,
                      float* __restrict__ outp) {
    __shared__ float sp[NB * DD];
    __shared__ float sz[NB * DD];
    int t = threadIdx.x;
#pragma unroll
    for (int j = 0; j < 4; j++) sp[t + 256 * j] = g_pooled[t + 256 * j];
    __syncthreads();
    int d = t & 127;
    int b0 = t >> 7;
    float acc[4];
#pragma unroll
    for (int j = 0; j < 4; j++) acc[j] = bias[d];
    for (int k = 0; k < DD; k++) {
        float wv = W[k * DD + d];
#pragma unroll
        for (int j = 0; j < 4; j++) acc[j] += sp[(b0 + 2 * j) * DD + k] * wv;
    }
#pragma unroll
    for (int j = 0; j < 4; j++) sz[(b0 + 2 * j) * DD + d] = acc[j];
    __syncthreads();
    int warp = t >> 5, lane = t & 31;
    float4 v = *reinterpret_cast<float4*>(&sz[warp * DD + lane * 4]);
    float4 u = ln128w(v, lg, lb, lane);
    outp[warp * DD + lane * 4 + 0] = geluf(u.x);
    outp[warp * DD + lane * 4 + 1] = geluf(u.y);
    outp[warp * DD + lane * 4 + 2] = geluf(u.z);
    outp[warp * DD + lane * 4 + 3] = geluf(u.w);
}

// ---------------- launch ----------------
extern "C" void kernel_launch(void* const* d_in, const int* in_sizes, int n_in,
                              void* d_out, int out_size) {
    const float* x        = (const float*)d_in[0];
    const int*   ei       = (const int*)d_in[1];
    const int*   batch    = (const int*)d_in[2];
    const float* w_in     = (const float*)d_in[3];
    const float* b_in     = (const float*)d_in[4];
    const float* ln_in_g  = (const float*)d_in[5];
    const float* ln_in_b  = (const float*)d_in[6];
    const float* gnn_w    = (const float*)d_in[7];
    const float* gnn_b    = (const float*)d_in[8];
    const float* gnn_ln_g = (const float*)d_in[9];
    const float* gnn_ln_b = (const float*)d_in[10];
    const float* norm_g   = (const float*)d_in[11];
    const float* norm_b   = (const float*)d_in[12];
    const float* gate_w1  = (const float*)d_in[13];
    const float* gate_b1  = (const float*)d_in[14];
    const float* gate_w2  = (const float*)d_in[15];
    const float* gate_b2  = (const float*)d_in[16];
    const float* out_w    = (const float*)d_in[17];
    const float* out_b    = (const float*)d_in[18];
    const float* out_ln_g = (const float*)d_in[19];
    const float* out_ln_b = (const float*)d_in[20];

    float* out = (float*)d_out;
    float* out_h    = (out_size >= NB * DD + NN * DD) ? out + NB * DD : nullptr;
    float* out_gate = (out_size >= NB * DD + NN * DD + NN) ? out + NB * DD + NN * DD : nullptr;

    cudaFuncSetAttribute((const void*)gemm_mma<64, 0>,
                         cudaFuncAttributeMaxDynamicSharedMemorySize, SMEM_DYN);
    cudaFuncSetAttribute((const void*)gemm_mma<256, 1>,
                         cudaFuncAttributeMaxDynamicSharedMemorySize, SMEM_DYN);
    cudaFuncSetAttribute((const void*)gemm_mma<128, 2>,
                         cudaFuncAttributeMaxDynamicSharedMemorySize, SMEM_DYN);

    const int GT = (NN + 127) / 128;
    const int GW = (NN * 32 + 255) / 256;
    const int GE = (NE + 255) / 256;

    // init + splits
    k_init<<<(NXP + 255) / 256, 256>>>(x, w_in, gnn_w, gate_w1);

    // CSR build
    k_count<<<GE, 256>>>(ei);
    k_scan1<<<NBLK, 256>>>();
    k_scan3<<<NBLK, 256>>>(batch);
    k_scatter<<<GE, 256>>>(ei);

    // input projection (+ fused LN->GELU)
    gemm_mma<64, 0><<<GT, 256, SMEM_DYN>>>(b_in, ln_in_g, ln_in_b, nullptr, nullptr,
                                           nullptr, 0, 0, NN);

    // GNN layers (+ fused GELU->LN->LN[->GELU+res])
    for (int l = 0; l < NL; l++) {
        k_aggregate<<<GW, 256>>>();
        gemm_mma<256, 1><<<GT, 256, SMEM_DYN>>>(gnn_b + l * 128,
                                                gnn_ln_g + l * 128, gnn_ln_b + l * 128,
                                                norm_g + l * 128, norm_b + l * 128,
                                                (l == NL - 1) ? out_h : nullptr,
                                                8192 + l * 32768,
                                                (l < NL - 1) ? 1 : 0, NN);
    }

    // gate (+ fused tanh + dot(w2) + exp-sum)
    gemm_mma<128, 2><<<GT, 256, SMEM_DYN>>>(gate_b1, gate_w2, nullptr, gate_b2, nullptr,
                                            nullptr, 106496, 0, NN);

    // pooling (gate inline, atomic)
    k_pool<<<NB * POOL_C, 128>>>(out_gate);

    // final projection
    k_out<<<1, 256>>>(out_w, out_b, out_ln_g, out_ln_b, out);
}

// round 6
// speedup vs baseline: 1.0070x; 1.0070x over previous
#include <cuda_runtime.h>
#include <cuda_bf16.h>
#include <cuda_fp16.h>
#include <math.h>
#include <stdint.h>

#define NN 50000
#define NE 800000
#define FIN 64
#define DD 128
#define NL 3
#define NB 8
#define POOL_C 64
#define NBLK 196          // ceil(NN/256)
#define WTOT 122880       // 128*64 + 3*128*256 + 128*128
#define NXP  1600000      // NN*FIN/2
#define ASTRIDE 72
#define SMEM_DYN 73728    // 4 * 128*72*2

// ---------------- scratch (device globals; no allocation) ----------------
__device__ __align__(16) __nv_bfloat16 g_hbh[NN * DD];   // h bf16 hi
__device__ __align__(16) __nv_bfloat16 g_hbl[NN * DD];   // h bf16 lo
__device__ __align__(16) __half g_hh[NN * DD];           // h fp16 (gathers)
__device__ __align__(16) __nv_bfloat16 g_abh[NN * DD];   // agg hi
__device__ __align__(16) __nv_bfloat16 g_abl[NN * DD];   // agg lo
__device__ __align__(16) __nv_bfloat16 g_xbh[NN * FIN];
__device__ __align__(16) __nv_bfloat16 g_xbl[NN * FIN];
__device__ __align__(16) __nv_bfloat16 g_wbh[WTOT];      // weights [n][k] hi
__device__ __align__(16) __nv_bfloat16 g_wbl[WTOT];      // lo
__device__ int   g_cnt[NN];
__device__ int   g_inc[NBLK * 256];
__device__ int   g_blksum[NBLK];
__device__ int   g_rowptr[NN + 1];
__device__ int   g_cursor[NN];
__device__ int   g_col[NE];
__device__ float g_deg[NN];
__device__ float g_logit[NN];
__device__ float g_sumexp;
__device__ int   g_bstart[NB + 1];
__device__ float g_pooled[NB * DD];

// ---------------- helpers ----------------
__device__ __forceinline__ float geluf(float x) {
    return 0.5f * x * (1.0f + erff(x * 0.7071067811865476f));
}
__device__ __forceinline__ float wsum(float v) {
#pragma unroll
    for (int o = 16; o > 0; o >>= 1) v += __shfl_xor_sync(0xffffffffu, v, o);
    return v;
}
__device__ __forceinline__ int wsumi(int v) {
#pragma unroll
    for (int o = 16; o > 0; o >>= 1) v += __shfl_xor_sync(0xffffffffu, v, o);
    return v;
}
__device__ __forceinline__ float qsum(float v) {
    v += __shfl_xor_sync(0xffffffffu, v, 1);
    v += __shfl_xor_sync(0xffffffffu, v, 2);
    return v;
}
__device__ __forceinline__ float4 ln128w(float4 v, const float* __restrict__ g,
                                         const float* __restrict__ b, int lane) {
    float m = wsum(v.x + v.y + v.z + v.w) * (1.0f / 128.0f);
    float dx = v.x - m, dy = v.y - m, dz = v.z - m, dw = v.w - m;
    float var = wsum(dx * dx + dy * dy + dz * dz + dw * dw) * (1.0f / 128.0f);
    float rs = rsqrtf(var + 1e-5f);
    float4 gg = *reinterpret_cast<const float4*>(g + lane * 4);
    float4 bb = *reinterpret_cast<const float4*>(b + lane * 4);
    return make_float4(dx * rs * gg.x + bb.x, dy * rs * gg.y + bb.y,
                       dz * rs * gg.z + bb.z, dw * rs * gg.w + bb.w);
}
__device__ __forceinline__ uint32_t smem_u32(const void* p) {
    uint32_t a;
    asm("{ .reg .u64 t; cvta.to.shared.u64 t, %1; cvt.u32.u64 %0, t; }" : "=r"(a) : "l"(p));
    return a;
}
__device__ __forceinline__ void ldm4(uint32_t* r, uint32_t addr) {
    asm volatile("ldmatrix.sync.aligned.m8n8.x4.shared.b16 {%0,%1,%2,%3}, [%4];"
                 : "=r"(r[0]), "=r"(r[1]), "=r"(r[2]), "=r"(r[3]) : "r"(addr));
}
__device__ __forceinline__ void mma16816(float* d, const uint32_t* a, uint32_t b0, uint32_t b1) {
    asm volatile(
        "mma.sync.aligned.m16n8k16.row.col.f32.bf16.bf16.f32 "
        "{%0,%1,%2,%3}, {%4,%5,%6,%7}, {%8,%9}, {%0,%1,%2,%3};"
        : "+f"(d[0]), "+f"(d[1]), "+f"(d[2]), "+f"(d[3])
        : "r"(a[0]), "r"(a[1]), "r"(a[2]), "r"(a[3]), "r"(b0), "r"(b1));
}
__device__ __forceinline__ uint32_t cvt2(float v0, float v1) {
    uint32_t d;
    asm("cvt.rn.bf16x2.f32 %0, %1, %2;" : "=r"(d) : "f"(v1), "f"(v0));
    return d;
}
__device__ __forceinline__ void split_pair(float v0, float v1, uint32_t& hi, uint32_t& lo) {
    hi = cvt2(v0, v1);
    float f0 = __uint_as_float(hi << 16);
    float f1 = __uint_as_float(hi & 0xFFFF0000u);
    lo = cvt2(v0 - f0, v1 - f1);
}

// ---------------- init: zero counters + split weights and x ----------------
__global__ void k_init(const float* __restrict__ x, const float* __restrict__ w_in,
                       const float* __restrict__ gnn_w, const float* __restrict__ gate_w1) {
    int i = blockIdx.x * blockDim.x + threadIdx.x;
    if (i < NXP) {
        float2 v = reinterpret_cast<const float2*>(x)[i];
        uint32_t hi, lo;
        split_pair(v.x, v.y, hi, lo);
        reinterpret_cast<uint32_t*>(g_xbh)[i] = hi;
        reinterpret_cast<uint32_t*>(g_xbl)[i] = lo;
    }
    if (i < WTOT / 2) {
        int j = 2 * i;
        float v0, v1;
        if (j < 8192) {
            int n = j >> 6, k = j & 63;
            v0 = w_in[k * 128 + n];
            v1 = w_in[(k + 1) * 128 + n];
        } else if (j < 106496) {
            int jj = j - 8192;
            int l = jj >> 15, r = jj & 32767;
            int n = r >> 8, k = r & 255;
            v0 = gnn_w[((l << 8) + k) * 128 + n];
            v1 = gnn_w[((l << 8) + k + 1) * 128 + n];
        } else {
            int jj = j - 106496;
            int n = jj >> 7, k = jj & 127;
            v0 = gate_w1[k * 128 + n];
            v1 = gate_w1[(k + 1) * 128 + n];
        }
        uint32_t hi, lo;
        split_pair(v0, v1, hi, lo);
        reinterpret_cast<uint32_t*>(g_wbh)[i] = hi;
        reinterpret_cast<uint32_t*>(g_wbl)[i] = lo;
    }
    if (i < NN) g_cnt[i] = 0;
    if (i < NB * DD) g_pooled[i] = 0.0f;
    if (i == 0) g_sumexp = 0.0f;
}

// ---------------- CSR build ----------------
__global__ void k_count(const int* __restrict__ ei) {
    int e = blockIdx.x * blockDim.x + threadIdx.x;
    if (e < NE) atomicAdd(&g_cnt[ei[NE + e]], 1);
}
__global__ void k_scan1() {
    __shared__ int sw_[8];
    int b = blockIdx.x, t = threadIdx.x, i = b * 256 + t;
    int v = (i < NN) ? g_cnt[i] : 0;
    int x = v;
#pragma unroll
    for (int o = 1; o < 32; o <<= 1) {
        int y = __shfl_up_sync(0xffffffffu, x, o);
        if ((t & 31) >= o) x += y;
    }
    if ((t & 31) == 31) sw_[t >> 5] = x;
    __syncthreads();
    if (t == 0) {
        int s = 0;
        for (int w = 0; w < 8; w++) { int tmp = sw_[w]; sw_[w] = s; s += tmp; }
    }
    __syncthreads();
    int incl = x + sw_[t >> 5];
    g_inc[b * 256 + t] = incl;
    if (t == 255) g_blksum[b] = incl;
}
__global__ void k_scan3(const int* __restrict__ batch) {
    __shared__ int soff;
    int blk = blockIdx.x, t = threadIdx.x;
    if (t < 32) {
        int s = 0;
        for (int b = t; b < blk; b += 32) s += g_blksum[b];
        s = wsumi(s);
        if (t == 0) soff = s;
    }
    __syncthreads();
    int i = blk * 256 + t;
    if (i < NN) {
        int incl = g_inc[i] + soff;
        int v = g_cnt[i];
        g_rowptr[i + 1] = incl;
        g_cursor[i] = incl - v;
        g_deg[i] = (v > 0) ? (float)v : 1.0f;
        if (i == 0) g_rowptr[0] = 0;
    }
    if (blk == 0 && t <= NB) {
        int lo = 0, hi = NN;
        while (lo < hi) {
            int mid = (lo + hi) >> 1;
            if (batch[mid] < t) lo = mid + 1; else hi = mid;
        }
        g_bstart[t] = lo;
    }
}
__global__ void k_scatter(const int* __restrict__ ei) {
    int e = blockIdx.x * blockDim.x + threadIdx.x;
    if (e < NE) {
        int d = ei[NE + e];
        int p = atomicAdd(&g_cursor[d], 1);
        g_col[p] = ei[e];
    }
}

// ---------------- HMMA GEMM (bf16 hi/lo 3-pass), pre-split operands, single buffer ----------------
// MODE 0: input proj (A = g_xbh/g_xbl): +bias -> LN -> GELU -> store h
// MODE 1: GNN layer (A = [g_hbh|g_abh] etc): +bias -> GELU -> LN -> LN [-> GELU+res] -> store h
// MODE 2: gate (A = g_hbh/g_hbl): tanh(v+bias).w2 -> logit + exp-sum atomic
template <int KD, int MODE>
__global__ void __launch_bounds__(256)
gemm_mma(const float* __restrict__ bias, const float* __restrict__ p1,
         const float* __restrict__ p2, const float* __restrict__ p3,
         const float* __restrict__ p4, float* __restrict__ aux,
         int boff, int residual, int nrows) {
    extern __shared__ __align__(16) char dyn[];
    __nv_bfloat16* As_h = (__nv_bfloat16*)dyn;         // [128][72]
    __nv_bfloat16* As_l = As_h + 128 * ASTRIDE;
    __nv_bfloat16* Bs_h = As_l + 128 * ASTRIDE;
    __nv_bfloat16* Bs_l = Bs_h + 128 * ASTRIDE;
    __shared__ float s0[128], s1[128], s2[128], s3[128], s4[128];
    __shared__ float sred[8];

    const int t = threadIdx.x;
    const int lane = t & 31, w = t >> 5;
    const int row0 = blockIdx.x * 128;

    if (t < 128) {
        s0[t] = bias[t];
        s1[t] = p1[t];
        if (MODE != 2) s2[t] = p2[t];
        if (MODE == 1) { s3[t] = p3[t]; s4[t] = p4[t]; }
    }

    constexpr int NCH = KD / 64;

    float acc[16][4];
#pragma unroll
    for (int i = 0; i < 16; i++)
#pragma unroll
        for (int j = 0; j < 4; j++) acc[i][j] = 0.0f;

    const uint32_t sA_h = smem_u32(As_h), sA_l = smem_u32(As_l);
    const uint32_t sB_h = smem_u32(Bs_h), sB_l = smem_u32(Bs_l);
    const uint32_t a_off = ((w * 16 + (lane & 15)) * ASTRIDE + (lane >> 4) * 8) * 2;
    const int bgq = lane >> 3;
    const uint32_t b_off = ((((bgq & 2) ? 8 : 0) + (lane & 7)) * ASTRIDE + ((bgq & 1) ? 8 : 0)) * 2;

#pragma unroll
    for (int c = 0; c < NCH; c++) {
#pragma unroll
        for (int q = 0; q < 4; q++) {
            int idx = q * 256 + t;       // 0..1023
            int r = idx >> 3, seg = idx & 7;
            const int row = row0 + r;
            const bool valid = row < nrows;
            const __nv_bfloat16 *pah, *pal;
            if (MODE == 0) {
                pah = g_xbh + (size_t)row * 64 + seg * 8;
                pal = g_xbl + (size_t)row * 64 + seg * 8;
            } else if (MODE == 2) {
                pah = g_hbh + (size_t)row * 128 + c * 64 + seg * 8;
                pal = g_hbl + (size_t)row * 128 + c * 64 + seg * 8;
            } else if (c < 2) {
                pah = g_hbh + (size_t)row * 128 + c * 64 + seg * 8;
                pal = g_hbl + (size_t)row * 128 + c * 64 + seg * 8;
            } else {
                pah = g_abh + (size_t)row * 128 + (c - 2) * 64 + seg * 8;
                pal = g_abl + (size_t)row * 128 + (c - 2) * 64 + seg * 8;
            }
            uint4 vh = make_uint4(0, 0, 0, 0), vl = make_uint4(0, 0, 0, 0);
            if (valid) {
                vh = *(const uint4*)pah;
                vl = *(const uint4*)pal;
            }
            *(uint4*)(As_h + r * ASTRIDE + seg * 8) = vh;
            *(uint4*)(As_l + r * ASTRIDE + seg * 8) = vl;
            const size_t wb = (size_t)boff + (size_t)r * KD + c * 64 + seg * 8;
            *(uint4*)(Bs_h + r * ASTRIDE + seg * 8) = *(const uint4*)(g_wbh + wb);
            *(uint4*)(Bs_l + r * ASTRIDE + seg * 8) = *(const uint4*)(g_wbl + wb);
        }
        __syncthreads();
#pragma unroll
        for (int kk = 0; kk < 64; kk += 16) {
            uint32_t aH[4], aL[4];
            ldm4(aH, sA_h + a_off + kk * 2);
            ldm4(aL, sA_l + a_off + kk * 2);
#pragma unroll
            for (int np = 0; np < 8; np++) {
                uint32_t bH[4], bL[4];
                uint32_t nb = (np * 16) * ASTRIDE * 2 + kk * 2;
                ldm4(bH, sB_h + b_off + nb);
                ldm4(bL, sB_l + b_off + nb);
                mma16816(acc[np * 2],     aH, bH[0], bH[1]);
                mma16816(acc[np * 2 + 1], aH, bH[2], bH[3]);
                mma16816(acc[np * 2],     aL, bH[0], bH[1]);
                mma16816(acc[np * 2 + 1], aL, bH[2], bH[3]);
                mma16816(acc[np * 2],     aH, bL[0], bL[1]);
                mma16816(acc[np * 2 + 1], aH, bL[2], bL[3]);
            }
        }
        __syncthreads();
    }

    // ---------------- fused epilogue ----------------
    const int qd = lane & 3;
    float esum = 0.f;
#pragma unroll
    for (int ri = 0; ri < 2; ri++) {
        const int row = row0 + w * 16 + (lane >> 2) + ri * 8;
        const bool ok = row < nrows;

        if (MODE == 2) {
            float p = 0.f;
#pragma unroll
            for (int j = 0; j < 32; j++) {
                int n = (j >> 1) * 8 + qd * 2 + (j & 1);
                p += tanhf(acc[j >> 1][ri * 2 + (j & 1)] + s0[n]) * s1[n];
            }
            p = qsum(p);
            if (qd == 0 && ok) {
                float lg = p + p3[0];
                g_logit[row] = lg;
                esum += expf(lg);
            }
            continue;
        }

        float v[32];
        float sum = 0.f;
#pragma unroll
        for (int j = 0; j < 32; j++) {
            int n = (j >> 1) * 8 + qd * 2 + (j & 1);
            float u = acc[j >> 1][ri * 2 + (j & 1)] + s0[n];
            if (MODE == 1) u = geluf(u);
            v[j] = u;
            sum += u;
        }
        float m1 = qsum(sum) * (1.0f / 128.0f);
        float var = 0.f;
#pragma unroll
        for (int j = 0; j < 32; j++) { float d = v[j] - m1; var += d * d; }
        float rs = rsqrtf(qsum(var) * (1.0f / 128.0f) + 1e-5f);

        if (MODE == 0) {
            if (ok) {
                uint32_t* ph = (uint32_t*)(g_hbh + (size_t)row * 128);
                uint32_t* pl = (uint32_t*)(g_hbl + (size_t)row * 128);
                uint32_t* phh = (uint32_t*)(g_hh + (size_t)row * 128);
#pragma unroll
                for (int k = 0; k < 16; k++) {
                    int n = k * 8 + qd * 2;
                    float o0 = geluf((v[2 * k] - m1) * rs * s1[n] + s2[n]);
                    float o1 = geluf((v[2 * k + 1] - m1) * rs * s1[n + 1] + s2[n + 1]);
                    uint32_t hi, lo;
                    split_pair(o0, o1, hi, lo);
                    ph[n >> 1] = hi;
                    pl[n >> 1] = lo;
                    __half2 hp = __floats2half2_rn(o0, o1);
                    phh[n >> 1] = *reinterpret_cast<uint32_t*>(&hp);
                }
            }
            continue;
        }

        // MODE 1: second LN
        float sum2 = 0.f;
#pragma unroll
        for (int j = 0; j < 32; j++) {
            int n = (j >> 1) * 8 + qd * 2 + (j & 1);
            float u = (v[j] - m1) * rs * s1[n] + s2[n];
            v[j] = u;
            sum2 += u;
        }
        float m2 = qsum(sum2) * (1.0f / 128.0f);
        float var2 = 0.f;
#pragma unroll
        for (int j = 0; j < 32; j++) { float d = v[j] - m2; var2 += d * d; }
        float rs2 = rsqrtf(qsum(var2) * (1.0f / 128.0f) + 1e-5f);

        if (ok) {
            uint32_t* ph = (uint32_t*)(g_hbh + (size_t)row * 128);
            uint32_t* pl = (uint32_t*)(g_hbl + (size_t)row * 128);
            uint32_t* phh = (uint32_t*)(g_hh + (size_t)row * 128);
            float2* arow = aux ? (float2*)(aux + (size_t)row * 128) : nullptr;
#pragma unroll
            for (int k = 0; k < 16; k++) {
                int n = k * 8 + qd * 2;
                float o0 = (v[2 * k] - m2) * rs2 * s3[n] + s4[n];
                float o1 = (v[2 * k + 1] - m2) * rs2 * s3[n + 1] + s4[n + 1];
                if (residual) {
                    uint32_t hprev = ph[n >> 1];
                    uint32_t lprev = pl[n >> 1];
                    float h0 = __uint_as_float(hprev << 16) + __uint_as_float(lprev << 16);
                    float h1 = __uint_as_float(hprev & 0xFFFF0000u) +
                               __uint_as_float(lprev & 0xFFFF0000u);
                    o0 = geluf(o0) + h0;
                    o1 = geluf(o1) + h1;
                }
                uint32_t hi, lo;
                split_pair(o0, o1, hi, lo);
                ph[n >> 1] = hi;
                pl[n >> 1] = lo;
                __half2 hp = __floats2half2_rn(o0, o1);
                phh[n >> 1] = *reinterpret_cast<uint32_t*>(&hp);
                if (arow) arow[n >> 1] = make_float2(o0, o1);
            }
        }
    }

    if (MODE == 2) {
        esum = wsum(esum);
        if (lane == 0) sred[w] = esum;
        __syncthreads();
        if (t == 0) {
            float tot = 0.f;
            for (int i = 0; i < 8; i++) tot += sred[i];
            atomicAdd(&g_sumexp, tot);
        }
    }
}

// ---------------- aggregation: mean over CSR neighbors (fp16 gather) -> bf16 hi/lo ----------------
__global__ void k_aggregate() {
    int gid = blockIdx.x * blockDim.x + threadIdx.x;
    int node = gid >> 5, lane = gid & 31;
    if (node >= NN) return;
    int s = g_rowptr[node], e = g_rowptr[node + 1];
    float4 acc = make_float4(0.f, 0.f, 0.f, 0.f);
    const uint2* hh = reinterpret_cast<const uint2*>(g_hh);
    for (int i = s; i < e; i++) {
        int src = g_col[i];
        uint2 v = hh[(size_t)src * 32 + lane];
        float2 f0 = __half22float2(*reinterpret_cast<__half2*>(&v.x));
        float2 f1 = __half22float2(*reinterpret_cast<__half2*>(&v.y));
        acc.x += f0.x; acc.y += f0.y; acc.z += f1.x; acc.w += f1.y;
    }
    float inv = 1.0f / g_deg[node];
    acc.x *= inv; acc.y *= inv; acc.z *= inv; acc.w *= inv;
    uint32_t h0, l0, h1, l1;
    split_pair(acc.x, acc.y, h0, l0);
    split_pair(acc.z, acc.w, h1, l1);
    size_t base = (size_t)node * 32 + lane;
    reinterpret_cast<uint2*>(g_abh)[base] = make_uint2(h0, h1);
    reinterpret_cast<uint2*>(g_abl)[base] = make_uint2(l0, l1);
}

// ---------------- pooling (gate inline, atomic accumulate) ----------------
__global__ void k_pool(float* __restrict__ out_gate) {
    int b = blockIdx.x / POOL_C;
    int c = blockIdx.x % POOL_C;
    int s = g_bstart[b], e = g_bstart[b + 1];
    long long len = e - s;
    int cs = s + (int)(len * c / POOL_C);
    int ce = s + (int)(len * (c + 1) / POOL_C);
    int d = threadIdx.x;
    float inv = 1.0f / g_sumexp;
    float acc = 0.f;
    for (int n = cs; n < ce; n++) {
        float gv = expf(g_logit[n]) * inv;
        float h = __bfloat162float(g_hbh[(size_t)n * DD + d]) +
                  __bfloat162float(g_hbl[(size_t)n * DD + d]);
        acc += gv * h;
        if (d == 0 && out_gate) out_gate[n] = gv;
    }
    atomicAdd(&g_pooled[b * DD + d], acc);
}

// ---------------- final out proj ----------------
__global__ void k_out(const float* __restrict__ W, const float* __restrict__ bias,
                      const float* __restrict__ lg, const float* __restrict__ lb,
                      float* __restrict__ outp) {
    __shared__ float sp[NB * DD];
    __shared__ float sz[NB * DD];
    int t = threadIdx.x;
#pragma unroll
    for (int j = 0; j < 4; j++) sp[t + 256 * j] = g_pooled[t + 256 * j];
    __syncthreads();
    int d = t & 127;
    int b0 = t >> 7;
    float acc[4];
#pragma unroll
    for (int j = 0; j < 4; j++) acc[j] = bias[d];
    for (int k = 0; k < DD; k++) {
        float wv = W[k * DD + d];
#pragma unroll
        for (int j = 0; j < 4; j++) acc[j] += sp[(b0 + 2 * j) * DD + k] * wv;
    }
#pragma unroll
    for (int j = 0; j < 4; j++) sz[(b0 + 2 * j) * DD + d] = acc[j];
    __syncthreads();
    int warp = t >> 5, lane = t & 31;
    float4 v = *reinterpret_cast<float4*>(&sz[warp * DD + lane * 4]);
    float4 u = ln128w(v, lg, lb, lane);
    outp[warp * DD + lane * 4 + 0] = geluf(u.x);
    outp[warp * DD + lane * 4 + 1] = geluf(u.y);
    outp[warp * DD + lane * 4 + 2] = geluf(u.z);
    outp[warp * DD + lane * 4 + 3] = geluf(u.w);
}

// ---------------- launch ----------------
extern "C" void kernel_launch(void* const* d_in, const int* in_sizes, int n_in,
                              void* d_out, int out_size) {
    const float* x        = (const float*)d_in[0];
    const int*   ei       = (const int*)d_in[1];
    const int*   batch    = (const int*)d_in[2];
    const float* w_in     = (const float*)d_in[3];
    const float* b_in     = (const float*)d_in[4];
    const float* ln_in_g  = (const float*)d_in[5];
    const float* ln_in_b  = (const float*)d_in[6];
    const float* gnn_w    = (const float*)d_in[7];
    const float* gnn_b    = (const float*)d_in[8];
    const float* gnn_ln_g = (const float*)d_in[9];
    const float* gnn_ln_b = (const float*)d_in[10];
    const float* norm_g   = (const float*)d_in[11];
    const float* norm_b   = (const float*)d_in[12];
    const float* gate_w1  = (const float*)d_in[13];
    const float* gate_b1  = (const float*)d_in[14];
    const float* gate_w2  = (const float*)d_in[15];
    const float* gate_b2  = (const float*)d_in[16];
    const float* out_w    = (const float*)d_in[17];
    const float* out_b    = (const float*)d_in[18];
    const float* out_ln_g = (const float*)d_in[19];
    const float* out_ln_b = (const float*)d_in[20];

    float* out = (float*)d_out;
    float* out_h    = (out_size >= NB * DD + NN * DD) ? out + NB * DD : nullptr;
    float* out_gate = (out_size >= NB * DD + NN * DD + NN) ? out + NB * DD + NN * DD : nullptr;

    cudaFuncSetAttribute((const void*)gemm_mma<64, 0>,
                         cudaFuncAttributeMaxDynamicSharedMemorySize, SMEM_DYN);
    cudaFuncSetAttribute((const void*)gemm_mma<256, 1>,
                         cudaFuncAttributeMaxDynamicSharedMemorySize, SMEM_DYN);
    cudaFuncSetAttribute((const void*)gemm_mma<128, 2>,
                         cudaFuncAttributeMaxDynamicSharedMemorySize, SMEM_DYN);

    const int GT = (NN + 127) / 128;
    const int GW = (NN * 32 + 255) / 256;
    const int GE = (NE + 255) / 256;

    // init + splits
    k_init<<<(NXP + 255) / 256, 256>>>(x, w_in, gnn_w, gate_w1);

    // CSR build
    k_count<<<GE, 256>>>(ei);
    k_scan1<<<NBLK, 256>>>();
    k_scan3<<<NBLK, 256>>>(batch);
    k_scatter<<<GE, 256>>>(ei);

    // input projection (+ fused LN->GELU)
    gemm_mma<64, 0><<<GT, 256, SMEM_DYN>>>(b_in, ln_in_g, ln_in_b, nullptr, nullptr,
                                           nullptr, 0, 0, NN);

    // GNN layers (+ fused GELU->LN->LN[->GELU+res])
    for (int l = 0; l < NL; l++) {
        k_aggregate<<<GW, 256>>>();
        gemm_mma<256, 1><<<GT, 256, SMEM_DYN>>>(gnn_b + l * 128,
                                                gnn_ln_g + l * 128, gnn_ln_b + l * 128,
                                                norm_g + l * 128, norm_b + l * 128,
                                                (l == NL - 1) ? out_h : nullptr,
                                                8192 + l * 32768,
                                                (l < NL - 1) ? 1 : 0, NN);
    }

    // gate (+ fused tanh + dot(w2) + exp-sum)
    gemm_mma<128, 2><<<GT, 256, SMEM_DYN>>>(gate_b1, gate_w2, nullptr, gate_b2, nullptr,
                                            nullptr, 106496, 0, NN);

    // pooling (gate inline, atomic)
    k_pool<<<NB * POOL_C, 128>>>(out_gate);

    // final projection
    k_out<<<1, 256>>>(out_w, out_b, out_ln_g, out_ln_b, out);
}